// round 1
// baseline (speedup 1.0000x reference)
#include <cuda_runtime.h>
#include <math.h>
#include <stdint.h>

#define BB 2
#define NNPTS 4096
#define CF 64
#define KNN 32
#define NTOT (BB*NNPTS)

// ---------------- scratch (static __device__, no allocs) ----------------
__device__ float g_K[(size_t)BB*NNPTS*NNPTS];   // 128 MB transport kernel
__device__ float g_f0n[NTOT*CF];
__device__ float g_f1n[NTOT*CF];
__device__ float g_n0[NTOT];
__device__ float g_n1[NTOT];
__device__ float g_colsum[NTOT];
__device__ float g_bvec[NTOT];
__device__ float g_otflow[NTOT*3];
__device__ int   g_idx[NTOT*KNN];
__device__ float g_x1[NTOT*32];
__device__ float g_x2[NTOT*64];

// ---------------- prep: feature normalize, point norms, colsum zero -----
__global__ __launch_bounds__(256)
void prep_kernel(const float* __restrict__ pc0, const float* __restrict__ pc1,
                 const float* __restrict__ f0, const float* __restrict__ f1)
{
    int w    = (blockIdx.x*blockDim.x + threadIdx.x) >> 5;
    int lane = threadIdx.x & 31;
    if (w >= 2*NTOT) return;
    int which = w / NTOT;       // 0: feats0, 1: feats1
    int row   = w % NTOT;
    const float* f = which ? f1 : f0;
    float v0 = f[row*CF + lane];
    float v1 = f[row*CF + 32 + lane];
    float ss = v0*v0 + v1*v1;
    #pragma unroll
    for (int o = 16; o > 0; o >>= 1) ss += __shfl_xor_sync(0xffffffffu, ss, o);
    float inv = rsqrtf(ss + 1e-8f);
    float* out = which ? g_f1n : g_f0n;
    out[row*CF + lane]      = v0*inv;
    out[row*CF + 32 + lane] = v1*inv;
    if (lane == 0) {
        const float* pc = which ? pc1 : pc0;
        float x = pc[row*3+0], y = pc[row*3+1], z = pc[row*3+2];
        float n2 = x*x + y*y + z*z;
        if (which) g_n1[row] = n2;
        else { g_n0[row] = n2; g_colsum[row] = 0.f; }
    }
}

// ---------------- K = exp(-(1 - f0n.f1n)/eps) * (sqdist<100), + colsums --
__global__ __launch_bounds__(256)
void kmat_kernel(const float* __restrict__ pc0, const float* __restrict__ pc1,
                 const float* __restrict__ epsilon)
{
    __shared__ float As[64][64];   // k-major: As[k][row]
    __shared__ float Bs[64][64];
    __shared__ float P0[3][64], P1[3][64];
    __shared__ float N0s[64], N1s[64];
    __shared__ float colpart[64];

    int bz = blockIdx.z;
    int row0 = blockIdx.y*64, col0 = blockIdx.x*64;
    int tid = threadIdx.x;

    {   // feature tiles, transpose into k-major smem
        int r = tid & 63, q = tid >> 6;                 // q in 0..3
        const float* a = g_f0n + (size_t)(bz*NNPTS + row0 + r)*CF + q*16;
        const float* b = g_f1n + (size_t)(bz*NNPTS + col0 + r)*CF + q*16;
        #pragma unroll
        for (int i = 0; i < 4; i++) {
            float4 va = *(const float4*)(a + 4*i);
            float4 vb = *(const float4*)(b + 4*i);
            int k = q*16 + 4*i;
            As[k+0][r]=va.x; As[k+1][r]=va.y; As[k+2][r]=va.z; As[k+3][r]=va.w;
            Bs[k+0][r]=vb.x; Bs[k+1][r]=vb.y; Bs[k+2][r]=vb.z; Bs[k+3][r]=vb.w;
        }
    }
    if (tid < 64) {
        int r = tid;
        #pragma unroll
        for (int d = 0; d < 3; d++) P0[d][r] = pc0[(bz*NNPTS+row0+r)*3 + d];
        N0s[r] = g_n0[bz*NNPTS + row0 + r];
        colpart[r] = 0.f;
    } else if (tid < 128) {
        int r = tid - 64;
        #pragma unroll
        for (int d = 0; d < 3; d++) P1[d][r] = pc1[(bz*NNPTS+col0+r)*3 + d];
        N1s[r] = g_n1[bz*NNPTS + col0 + r];
    }
    __syncthreads();

    int rb = (tid >> 4)*4, cb = (tid & 15)*4;
    float acc[4][4];  float accp[4][4];
    #pragma unroll
    for (int i=0;i<4;i++) { acc[i][0]=acc[i][1]=acc[i][2]=acc[i][3]=0.f;
                            accp[i][0]=accp[i][1]=accp[i][2]=accp[i][3]=0.f; }
    #pragma unroll 4
    for (int k = 0; k < 64; k++) {
        float4 a = *(const float4*)&As[k][rb];
        float4 b = *(const float4*)&Bs[k][cb];
        float ar[4] = {a.x,a.y,a.z,a.w}, br[4] = {b.x,b.y,b.z,b.w};
        #pragma unroll
        for (int i=0;i<4;i++)
            #pragma unroll
            for (int j=0;j<4;j++) acc[i][j] = fmaf(ar[i], br[j], acc[i][j]);
    }
    #pragma unroll
    for (int k = 0; k < 3; k++) {
        float4 a = *(const float4*)&P0[k][rb];
        float4 b = *(const float4*)&P1[k][cb];
        float ar[4] = {a.x,a.y,a.z,a.w}, br[4] = {b.x,b.y,b.z,b.w};
        #pragma unroll
        for (int i=0;i<4;i++)
            #pragma unroll
            for (int j=0;j<4;j++) accp[i][j] = fmaf(ar[i], br[j], accp[i][j]);
    }

    float eps = expf(epsilon[0]) + 0.025f;
    float inv_eps = 1.0f/eps;
    float cs[4] = {0.f,0.f,0.f,0.f};
    #pragma unroll
    for (int i = 0; i < 4; i++) {
        float n0v = N0s[rb+i];
        float kv[4];
        #pragma unroll
        for (int j = 0; j < 4; j++) {
            float sqd = n0v + N1s[cb+j] - 2.0f*accp[i][j];
            float Cv  = 1.0f - acc[i][j];
            float v   = (sqd < 100.0f) ? expf(-Cv*inv_eps) : 0.0f;
            kv[j] = v; cs[j] += v;
        }
        float4 o = make_float4(kv[0],kv[1],kv[2],kv[3]);
        *(float4*)&g_K[((size_t)(bz*NNPTS) + row0 + rb + i)*NNPTS + col0 + cb] = o;
    }
    #pragma unroll
    for (int j = 0; j < 4; j++) atomicAdd(&colpart[cb+j], cs[j]);
    __syncthreads();
    if (tid < 64) atomicAdd(&g_colsum[bz*NNPTS + col0 + tid], colpart[tid]);
}

// ---------------- b = (prob2/(K^T a + 1e-8))^power -----------------------
__global__ __launch_bounds__(256)
void bvec_kernel(const float* __restrict__ gamma, const float* __restrict__ epsilon)
{
    int i = blockIdx.x*blockDim.x + threadIdx.x;
    if (i >= NTOT) return;
    float eps = expf(epsilon[0]) + 0.025f;
    float gam = expf(gamma[0]);
    float power = gam/(gam+eps);
    float kta = g_colsum[i] * (1.0f/NNPTS);
    g_bvec[i] = powf((1.0f/NNPTS)/(kta + 1e-8f), power);
}

// ---------------- row pass: Kb, K b pc1 -> ot_flow ------------------------
__global__ __launch_bounds__(256)
void rowpass_kernel(const float* __restrict__ pc0, const float* __restrict__ pc1,
                    const float* __restrict__ gamma, const float* __restrict__ epsilon)
{
    int n = blockIdx.x; int b = n / NNPTS; int nl = n % NNPTS;
    const float* Kr = g_K + ((size_t)(b*NNPTS) + nl)*NNPTS;
    const float* bp = g_bvec + b*NNPTS;
    const float* p1 = pc1 + b*NNPTS*3;
    float kb=0.f, sx=0.f, sy=0.f, sz=0.f;
    for (int m = threadIdx.x; m < NNPTS; m += 256) {
        float w = Kr[m]*bp[m];
        kb += w;
        sx = fmaf(w, p1[m*3+0], sx);
        sy = fmaf(w, p1[m*3+1], sy);
        sz = fmaf(w, p1[m*3+2], sz);
    }
    #pragma unroll
    for (int o = 16; o > 0; o >>= 1) {
        kb += __shfl_xor_sync(0xffffffffu, kb, o);
        sx += __shfl_xor_sync(0xffffffffu, sx, o);
        sy += __shfl_xor_sync(0xffffffffu, sy, o);
        sz += __shfl_xor_sync(0xffffffffu, sz, o);
    }
    __shared__ float rbuf[8][4];
    int w = threadIdx.x >> 5, lane = threadIdx.x & 31;
    if (lane == 0) { rbuf[w][0]=kb; rbuf[w][1]=sx; rbuf[w][2]=sy; rbuf[w][3]=sz; }
    __syncthreads();
    if (threadIdx.x == 0) {
        float Kb=0.f,Sx=0.f,Sy=0.f,Sz=0.f;
        #pragma unroll
        for (int i=0;i<8;i++){ Kb+=rbuf[i][0]; Sx+=rbuf[i][1]; Sy+=rbuf[i][2]; Sz+=rbuf[i][3]; }
        float eps = expf(epsilon[0]) + 0.025f;
        float gam = expf(gamma[0]);
        float power = gam/(gam+eps);
        float a  = powf((1.0f/NNPTS)/(Kb + 1e-8f), power);
        float rs = a*Kb;
        float inv = 1.0f/(rs + 1e-8f);
        g_otflow[n*3+0] = a*Sx*inv - pc0[n*3+0];
        g_otflow[n*3+1] = a*Sy*inv - pc0[n*3+1];
        g_otflow[n*3+2] = a*Sz*inv - pc0[n*3+2];
    }
}

// ---------------- KNN: radix-select 32 smallest sqdists per row ----------
__global__ __launch_bounds__(256)
void knn_kernel(const float* __restrict__ pc0)
{
    int n = blockIdx.x; int b = n / NNPTS; int nl = n % NNPTS;
    const float* pc = pc0 + b*NNPTS*3;
    const float* n0 = g_n0 + b*NNPTS;
    int tid = threadIdx.x;
    float qx = pc[nl*3+0], qy = pc[nl*3+1], qz = pc[nl*3+2];
    float qn = n0[nl];
    unsigned key[16];
    #pragma unroll
    for (int i = 0; i < 16; i++) {
        int m = tid + i*256;
        float px = pc[m*3+0], py = pc[m*3+1], pz = pc[m*3+2];
        float dot = px*qx + py*qy + pz*qz;
        float d = qn + n0[m] - 2.0f*dot;
        unsigned u = __float_as_uint(d);
        u = (u & 0x80000000u) ? ~u : (u | 0x80000000u);
        key[i] = u;
    }
    __shared__ int hist[256];
    __shared__ unsigned s_prefix;
    __shared__ int s_krem, s_cl, s_ct;
    __shared__ int s_out[KNN];
    __shared__ int s_tie[64];
    if (tid == 0) { s_prefix = 0u; s_krem = KNN; s_cl = 0; s_ct = 0; }
    for (int r = 0; r < 4; r++) {
        int shift = 24 - 8*r;
        hist[tid] = 0;
        __syncthreads();
        unsigned pref = s_prefix;
        unsigned msk  = (r == 0) ? 0u : (0xFFFFFFFFu << (32 - 8*r));
        #pragma unroll
        for (int i = 0; i < 16; i++)
            if ((key[i] & msk) == (pref & msk))
                atomicAdd(&hist[(key[i] >> shift) & 255], 1);
        __syncthreads();
        if (tid == 0) {
            int krem = s_krem, cum = 0, d = 0;
            for (; d < 256; d++) { int c = hist[d]; if (cum + c >= krem) break; cum += c; }
            s_prefix = pref | ((unsigned)d << shift);
            s_krem = krem - cum;
        }
        __syncthreads();
    }
    unsigned pivot = s_prefix;
    #pragma unroll
    for (int i = 0; i < 16; i++) {
        unsigned u = key[i];
        if (u < pivot)       { int p = atomicAdd(&s_cl, 1); s_out[p] = tid + i*256; }
        else if (u == pivot) { int t = atomicAdd(&s_ct, 1); if (t < 64) s_tie[t] = tid + i*256; }
    }
    __syncthreads();
    if (tid == 0) {
        int cl = s_cl;
        int nt = (s_ct < 64) ? s_ct : 64;
        int need = KNN - cl;                 // ties filled by lowest index (jax tie-break)
        for (int s = 0; s < need; s++) {
            int best = 0x7FFFFFFF, bi = 0;
            for (int t = 0; t < nt; t++) if (s_tie[t] < best) { best = s_tie[t]; bi = t; }
            s_tie[bi] = 0x7FFFFFFF;
            s_out[cl + s] = best;
        }
    }
    __syncthreads();
    if (tid < KNN) g_idx[n*KNN + tid] = s_out[tid];
}

// ---------------- fused set-conv layer (edge GEMM + max + 2 dense) -------
__device__ __forceinline__ float lrelu(float x){ return (x > 0.f) ? x : 0.1f*x; }

template<int LAYER>
__global__ __launch_bounds__(128)
void conv_kernel(const float* __restrict__ pc0,
                 const float* __restrict__ W1, const float* __restrict__ B1,
                 const float* __restrict__ W2, const float* __restrict__ B2,
                 const float* __restrict__ W3, const float* __restrict__ B3,
                 const float* __restrict__ Wfc, const float* __restrict__ Bfc,
                 float* __restrict__ dout)
{
    constexpr int CIN  = (LAYER==0) ? 3 : (LAYER==1) ? 32 : 64;
    constexpr int C    = (LAYER==0) ? 32 : (LAYER==1) ? 64 : 128;
    constexpr bool FIN = (LAYER==2);
    constexpr int NPB  = 128 / C;
    constexpr int KTOT = CIN + 3;
    constexpr int K4   = (KTOT + 3) & ~3;
    constexpr int KM   = KTOT & ~3;

    __shared__ __align__(16) float in_s[NPB][KNN][K4];
    __shared__ float h1[NPB][C];
    __shared__ float h2[NPB][C];
    __shared__ int   nb_s[NPB][KNN];

    const float* feat_in = (LAYER==0) ? g_otflow : (LAYER==1) ? g_x1 : g_x2;
    float* feat_out = (LAYER==0) ? g_x1 : g_x2;

    int tid = threadIdx.x;
    int g = tid / C, c = tid % C;
    int node = blockIdx.x * NPB + g;
    int b = node / NNPTS;

    if (c < KNN) nb_s[g][c] = g_idx[node*KNN + c];
    __syncthreads();

    for (int e = c; e < KNN*KTOT; e += C) {
        int j = e / KTOT, k = e % KTOT;
        int nb = nb_s[g][j];
        float v;
        if (k < CIN) v = feat_in[(size_t)(b*NNPTS + nb)*CIN + k];
        else {
            int d = k - CIN;
            v = pc0[(b*NNPTS + nb)*3 + d] - pc0[node*3 + d];
        }
        in_s[g][j][k] = v;
    }
    __syncthreads();

    // edge layer: acc over KNN neighbors, channel c
    float acc[KNN];
    float bias1 = B1[c];
    #pragma unroll
    for (int j = 0; j < KNN; j++) acc[j] = bias1;
    for (int k = 0; k < KM; k += 4) {
        float w0 = W1[(k+0)*C + c];
        float w1 = W1[(k+1)*C + c];
        float w2 = W1[(k+2)*C + c];
        float w3 = W1[(k+3)*C + c];
        #pragma unroll
        for (int j = 0; j < KNN; j++) {
            float4 iv = *(const float4*)&in_s[g][j][k];
            acc[j] = fmaf(iv.x, w0, acc[j]);
            acc[j] = fmaf(iv.y, w1, acc[j]);
            acc[j] = fmaf(iv.z, w2, acc[j]);
            acc[j] = fmaf(iv.w, w3, acc[j]);
        }
    }
    for (int k = KM; k < KTOT; k++) {
        float w = W1[k*C + c];
        #pragma unroll
        for (int j = 0; j < KNN; j++) acc[j] = fmaf(in_s[g][j][k], w, acc[j]);
    }
    float mx = -3.4e38f;
    #pragma unroll
    for (int j = 0; j < KNN; j++) mx = fmaxf(mx, lrelu(acc[j]));
    h1[g][c] = mx;
    __syncthreads();

    float a2 = B2[c];
    for (int k = 0; k < C; k++) a2 = fmaf(h1[g][k], W2[k*C + c], a2);
    a2 = lrelu(a2);
    h2[g][c] = a2;
    __syncthreads();

    float a3 = B3[c];
    for (int k = 0; k < C; k++) a3 = fmaf(h2[g][k], W3[k*C + c], a3);
    a3 = lrelu(a3);

    if (!FIN) {
        feat_out[(size_t)node*C + c] = a3;
    } else {
        h1[g][c] = a3;
        __syncthreads();
        if (c < 3) {
            float o = Bfc[c];
            for (int k = 0; k < C; k++) o = fmaf(h1[g][k], Wfc[k*3 + c], o);
            dout[node*3 + c] = g_otflow[node*3 + c] + o;
        }
    }
}

// ---------------- launch --------------------------------------------------
extern "C" void kernel_launch(void* const* d_in, const int* in_sizes, int n_in,
                              void* d_out, int out_size)
{
    const float* pc0   = (const float*)d_in[0];
    const float* pc1   = (const float*)d_in[1];
    const float* f0    = (const float*)d_in[2];
    const float* f1    = (const float*)d_in[3];
    const float* gamma = (const float*)d_in[4];
    const float* eps   = (const float*)d_in[5];
    const float* w1_1=(const float*)d_in[6],  *b1_1=(const float*)d_in[7];
    const float* w1_2=(const float*)d_in[8],  *b1_2=(const float*)d_in[9];
    const float* w1_3=(const float*)d_in[10], *b1_3=(const float*)d_in[11];
    const float* w2_1=(const float*)d_in[12], *b2_1=(const float*)d_in[13];
    const float* w2_2=(const float*)d_in[14], *b2_2=(const float*)d_in[15];
    const float* w2_3=(const float*)d_in[16], *b2_3=(const float*)d_in[17];
    const float* w3_1=(const float*)d_in[18], *b3_1=(const float*)d_in[19];
    const float* w3_2=(const float*)d_in[20], *b3_2=(const float*)d_in[21];
    const float* w3_3=(const float*)d_in[22], *b3_3=(const float*)d_in[23];
    const float* wfc =(const float*)d_in[24], *bfc =(const float*)d_in[25];
    float* out = (float*)d_out;

    prep_kernel<<<2048, 256>>>(pc0, pc1, f0, f1);
    kmat_kernel<<<dim3(NNPTS/64, NNPTS/64, BB), 256>>>(pc0, pc1, eps);
    bvec_kernel<<<(NTOT + 255)/256, 256>>>(gamma, eps);
    rowpass_kernel<<<NTOT, 256>>>(pc0, pc1, gamma, eps);
    knn_kernel<<<NTOT, 256>>>(pc0);
    conv_kernel<0><<<NTOT/4, 128>>>(pc0, w1_1,b1_1, w1_2,b1_2, w1_3,b1_3, wfc,bfc, out);
    conv_kernel<1><<<NTOT/2, 128>>>(pc0, w2_1,b2_1, w2_2,b2_2, w2_3,b2_3, wfc,bfc, out);
    conv_kernel<2><<<NTOT,   128>>>(pc0, w3_1,b3_1, w3_2,b3_2, w3_3,b3_3, wfc,bfc, out);
}